// round 15
// baseline (speedup 1.0000x reference)
#include <cuda_runtime.h>
#include <cuda_fp16.h>
#include <math.h>
#include <stdint.h>

#define NG      64
#define N_ORIG  1984
#define NN      2048
#define DD      512
#define NH      8
#define DKH     64
#define FFD     2048
#define NL      4
#define NFE     32
#define MAX_SP  100
#define MAX_DEG 100
#define QKVW    1536

// ---------- scratch ----------
__device__ float  g_h[NN * DD];
__device__ __half g_hn[NN * DD];
__device__ __half g_qkv[NN * QKVW];
__device__ __half g_attn[NN * DD];
__device__ __half g_ff[(size_t)NN * FFD];
__device__ __half g_WqkvT[NL * QKVW * DD];
__device__ float  g_bqkv[NL * QKVW];
__device__ __half g_WoT[NL * DD * DD];
__device__ __half g_W1T[NL * DD * FFD];
__device__ __half g_W2T[NL * FFD * DD];

// ---------- helpers ----------
__device__ __forceinline__ uint32_t smem_u32(const void* p) {
    uint32_t a;
    asm("{ .reg .u64 t; cvta.to.shared.u64 t, %1; cvt.u32.u64 %0, t; }" : "=r"(a) : "l"(p));
    return a;
}
__device__ __forceinline__ void cp_async16(uint32_t d, const void* g) {
    asm volatile("cp.async.cg.shared.global [%0], [%1], 16;" :: "r"(d), "l"(g));
}
__device__ __forceinline__ void cp_commit() { asm volatile("cp.async.commit_group;" ::: "memory"); }
__device__ __forceinline__ void cp_wait1()  { asm volatile("cp.async.wait_group 1;"  ::: "memory"); }
__device__ __forceinline__ void cp_wait0()  { asm volatile("cp.async.wait_group 0;"  ::: "memory"); }

#define LDSM4(r0, r1, r2, r3, addr) \
    asm volatile("ldmatrix.sync.aligned.m8n8.x4.shared.b16 {%0,%1,%2,%3}, [%4];" \
        : "=r"(r0), "=r"(r1), "=r"(r2), "=r"(r3) : "r"(addr))

__device__ __forceinline__ void mma16(float* c, const uint32_t* a, const uint32_t* b) {
    asm volatile(
        "mma.sync.aligned.m16n8k16.row.col.f32.f16.f16.f32 "
        "{%0,%1,%2,%3}, {%4,%5,%6,%7}, {%8,%9}, {%0,%1,%2,%3};"
        : "+f"(c[0]), "+f"(c[1]), "+f"(c[2]), "+f"(c[3])
        : "r"(a[0]), "r"(a[1]), "r"(a[2]), "r"(a[3]), "r"(b[0]), "r"(b[1]));
}

// ---------- small kernels ----------
__global__ void init_h_kernel(const float* __restrict__ x, const float* __restrict__ W,
                              const float* __restrict__ b, const float* __restrict__ cent,
                              const int* __restrict__ deg)
{
    int idx = blockIdx.x * blockDim.x + threadIdx.x;
    if (idx >= NN * DD) return;
    int n = idx / DD, d = idx % DD;
    float v = 0.f;
    if (n < N_ORIG) {
        v = b[d];
        #pragma unroll
        for (int f = 0; f < NFE; f++) v += x[n * NFE + f] * W[f * DD + d];
    }
    g_h[idx] = v + cent[min(deg[n], MAX_DEG) * DD + d];
}

// LN; one WARP per row, 8 rows/CTA, fp32 in -> fp16 out
__global__ void __launch_bounds__(256)
ln_kernel(const float* __restrict__ in, __half* __restrict__ out)
{
    const int w = threadIdx.x >> 5, lane = threadIdx.x & 31;
    const int row = blockIdx.x * 8 + w;
    const float* p = in + (size_t)row * DD;
    float4 v[4];
    float a = 0.f, q = 0.f;
    #pragma unroll
    for (int i = 0; i < 4; i++) {
        v[i] = *(const float4*)(p + i * 128 + lane * 4);
        a += v[i].x + v[i].y + v[i].z + v[i].w;
        q += v[i].x * v[i].x + v[i].y * v[i].y + v[i].z * v[i].z + v[i].w * v[i].w;
    }
    #pragma unroll
    for (int o = 16; o; o >>= 1) {
        a += __shfl_xor_sync(~0u, a, o);
        q += __shfl_xor_sync(~0u, q, o);
    }
    float mean = a * (1.f / DD);
    float var  = q * (1.f / DD) - mean * mean;
    float r = rsqrtf(var + 1e-5f);
    __half* o = out + (size_t)row * DD;
    #pragma unroll
    for (int i = 0; i < 4; i++) {
        int j = i * 128 + lane * 4;
        *(__half2*)(o + j)     = __floats2half2_rn((v[i].x - mean) * r, (v[i].y - mean) * r);
        *(__half2*)(o + j + 2) = __floats2half2_rn((v[i].z - mean) * r, (v[i].w - mean) * r);
    }
}

// ---------- fast 64x64 transpose, fp32 -> fp16 (stride 68) ----------
__global__ void __launch_bounds__(256)
fast_transpose(const float* __restrict__ in, __half* __restrict__ out, int R, int C)
{
    __shared__ float t[64][68];
    in  += (size_t)blockIdx.z * R * C;
    out += (size_t)blockIdx.z * R * C;
    const int c0 = blockIdx.x * 64, r0 = blockIdx.y * 64;
    const int tid = threadIdx.x;

    int lr = tid >> 4, lc4 = tid & 15;
    #pragma unroll
    for (int i = 0; i < 4; i++) {
        int r = lr + i * 16;
        float4 v = *(const float4*)(in + (size_t)(r0 + r) * C + c0 + lc4 * 4);
        *(float4*)&t[r][lc4 * 4] = v;
    }
    __syncthreads();

    int c = tid >> 2, s = tid & 3;
    __half* orow = out + (size_t)(c0 + c) * R + r0;
    #pragma unroll
    for (int jj = 0; jj < 8; jj++) {
        int rr = jj * 8 + s * 2;
        *(__half2*)(orow + rr) = __floats2half2_rn(t[rr][c], t[rr + 1][c]);
    }
}

__global__ void __launch_bounds__(256)
fast_pack_qkvT(const float* __restrict__ Wq, const float* __restrict__ Wk,
               const float* __restrict__ Wv, __half* __restrict__ out)
{
    __shared__ float t[64][68];
    int z = blockIdx.z;
    int h = z & 7, qkv = (z >> 3) % 3, l = z / 24;
    const float* src = (qkv == 0 ? Wq : qkv == 1 ? Wk : Wv) + (size_t)(l * NH + h) * DD * DKH;
    __half* dst = out + (size_t)l * QKVW * DD + (size_t)(qkv * DD + h * DKH) * DD;
    const int r0 = blockIdx.y * 64;
    const int tid = threadIdx.x;

    int lr = tid >> 4, lc4 = tid & 15;
    #pragma unroll
    for (int i = 0; i < 4; i++) {
        int r = lr + i * 16;
        float4 v = *(const float4*)(src + (size_t)(r0 + r) * DKH + lc4 * 4);
        *(float4*)&t[r][lc4 * 4] = v;
    }
    __syncthreads();

    int c = tid >> 2, s = tid & 3;
    __half* orow = dst + (size_t)c * DD + r0;
    #pragma unroll
    for (int jj = 0; jj < 8; jj++) {
        int rr = jj * 8 + s * 2;
        *(__half2*)(orow + rr) = __floats2half2_rn(t[rr][c], t[rr + 1][c]);
    }
}

__global__ void pack_bias(const float* __restrict__ bq, const float* __restrict__ bk,
                          const float* __restrict__ bv, float* __restrict__ out)
{
    int idx = blockIdx.x * blockDim.x + threadIdx.x;
    if (idx >= NL * QKVW) return;
    int l = idx / QKVW, p = idx % QKVW;
    float v;
    if (p < DD)            v = bq[l * DD + p];
    else if (p < 2 * DD)   v = bk[l * DD + p - DD];
    else                   v = bv[l * DD + p - 2 * DD];
    out[idx] = v;
}

// ---------- fused block-diagonal attention ----------
__global__ void __launch_bounds__(128)
attn_fused(const __half* __restrict__ qkv, __half* __restrict__ O,
           const int* __restrict__ sp, const float* __restrict__ db,
           const float* __restrict__ vb, float scale, int only_virt)
{
    __shared__ float Ks[32][68];
    __shared__ float Vs[32][68];
    __shared__ float Bs[32][33];
    __shared__ float Ps[32][33];

    const int g = blockIdx.x, h = blockIdx.y;
    const int t = threadIdx.x;
    const int r = t >> 2, q4 = t & 3;

    for (int u = t; u < 1024; u += 128) {
        int rr = u >> 5, cc = u & 31;
        int i = (rr < 31) ? g * 31 + rr : N_ORIG + g;
        int j = (cc < 31) ? g * 31 + cc : N_ORIG + g;
        float bvv;
        if (i == j)                        bvv = db[0];
        else if ((rr == 31) != (cc == 31)) bvv = vb[0];
        else                               bvv = db[min(sp[(size_t)i * N_ORIG + j], MAX_SP)];
        Bs[rr][cc] = bvv;
    }

    {
        int n = (r < 31) ? g * 31 + r : N_ORIG + g;
        int d0 = q4 * 16;
        const __half2* kp = (const __half2*)(qkv + (size_t)n * QKVW + DD + h * DKH + d0);
        const __half2* vp = (const __half2*)(qkv + (size_t)n * QKVW + 2 * DD + h * DKH + d0);
        #pragma unroll
        for (int i = 0; i < 8; i++) {
            float2 kf = __half22float2(kp[i]);
            Ks[r][d0 + 2 * i] = kf.x; Ks[r][d0 + 2 * i + 1] = kf.y;
            float2 vf = __half22float2(vp[i]);
            Vs[r][d0 + 2 * i] = vf.x; Vs[r][d0 + 2 * i + 1] = vf.y;
        }
    }
    __syncthreads();

    {
        int nr = (r < 31) ? g * 31 + r : N_ORIG + g;
        const __half2* qp = (const __half2*)(qkv + (size_t)nr * QKVW + h * DKH);
        float2 qv[32];
        #pragma unroll
        for (int i = 0; i < 32; i++) qv[i] = __half22float2(qp[i]);

        float s[8];
        #pragma unroll
        for (int cc = 0; cc < 8; cc++) {
            int c = q4 + 4 * cc;
            const float2* kr = (const float2*)&Ks[c][0];
            float acc = 0.f;
            #pragma unroll
            for (int i = 0; i < 32; i++) {
                float2 k2 = kr[i];
                acc += qv[i].x * k2.x + qv[i].y * k2.y;
            }
            s[cc] = acc * scale + Bs[r][c];
        }
        float m = s[0];
        #pragma unroll
        for (int cc = 1; cc < 8; cc++) m = fmaxf(m, s[cc]);
        m = fmaxf(m, __shfl_xor_sync(~0u, m, 1));
        m = fmaxf(m, __shfl_xor_sync(~0u, m, 2));
        float sum = 0.f;
        #pragma unroll
        for (int cc = 0; cc < 8; cc++) { s[cc] = __expf(s[cc] - m); sum += s[cc]; }
        sum += __shfl_xor_sync(~0u, sum, 1);
        sum += __shfl_xor_sync(~0u, sum, 2);
        float inv = 1.f / sum;
        #pragma unroll
        for (int cc = 0; cc < 8; cc++) Ps[r][q4 + 4 * cc] = s[cc] * inv;
    }
    __syncthreads();

    if (!only_virt || r == 31) {
        float acc[16];
        #pragma unroll
        for (int i = 0; i < 16; i++) acc[i] = 0.f;
        #pragma unroll
        for (int c = 0; c < 32; c++) {
            float p = Ps[r][c];
            #pragma unroll
            for (int i = 0; i < 8; i++) {
                float2 v2 = *(const float2*)&Vs[c][8 * i + 2 * q4];
                acc[2 * i]     += p * v2.x;
                acc[2 * i + 1] += p * v2.y;
            }
        }
        int n = (r < 31) ? g * 31 + r : N_ORIG + g;
        __half* op = O + (size_t)n * DD + h * DKH;
        #pragma unroll
        for (int i = 0; i < 8; i++)
            *(__half2*)(op + 8 * i + 2 * q4) = __floats2half2_rn(acc[2 * i], acc[2 * i + 1]);
    }
}

// ---------- staging: rows of KCH fp16, chunk-swizzled ----------
template<int TM, int TN, int KCH>
__device__ __forceinline__ void load_tiles_h(const __half* A, int lda, const __half* Bt, int ldb,
        int row0, int col0, int k0, uint32_t aS, uint32_t bS, int tid)
{
    constexpr int CH = KCH / 8;
    constexpr int ROWB = KCH * 2;
    #pragma unroll
    for (int i = 0; i < TM * CH / 256; i++) {
        int u = tid + i * 256;
        int r = u / CH, c = u % CH;
        uint32_t sc = (uint32_t)((((c ^ r) & 7) | (c & ~7)));
        cp_async16(aS + (uint32_t)r * ROWB + (sc << 4),
                   A + (size_t)(row0 + r) * lda + k0 + c * 8);
    }
    #pragma unroll
    for (int i = 0; i < TN * CH / 256; i++) {
        int u = tid + i * 256;
        int r = u / CH, c = u % CH;
        uint32_t sc = (uint32_t)((((c ^ r) & 7) | (c & ~7)));
        cp_async16(bS + (uint32_t)r * ROWB + (sc << 4),
                   Bt + (size_t)(col0 + r) * ldb + k0 + c * 8);
    }
}

// ---------- fp16 mma m16n8k16 NT GEMM, compile-time K, occ 3 ----------
// MODE 3: C=fp32 +bias+res | 4: C16=fp16 relu(+bias) | 6: C16=fp16 +bias
template<int TM, int TN, int KCH, int KTOT, int MODE>
__global__ void __launch_bounds__(256, 3)
gemm_h(const __half* __restrict__ A, int lda,
       const __half* __restrict__ Bt, int ldb,
       float* __restrict__ C, __half* __restrict__ C16, int ldc,
       const float* __restrict__ bias,
       const float* __restrict__ res)
{
    constexpr int WROWS = TM / 4;
    constexpr int MT = WROWS / 16;
    constexpr int NT = TN / 16;
    constexpr int CH = KCH / 8;
    constexpr int NC = KTOT / KCH;
    constexpr uint32_t ROWB = (uint32_t)KCH * 2u;
    constexpr uint32_t STAGE = (uint32_t)(TM + TN) * ROWB;

    extern __shared__ char smraw[];
    uint32_t rawu = smem_u32(smraw);
    uint32_t base = (rawu + 127u) & ~127u;

    const int tid = threadIdx.x;
    const int col0 = blockIdx.x * TN;
    const int row0 = blockIdx.y * TM;

    const int w = tid >> 5, lane = tid & 31;
    const int wr = w >> 1, wc = w & 1;
    const int g = lane >> 2, cq = lane & 3;

    float acc[MT][NT][4];
    #pragma unroll
    for (int mt = 0; mt < MT; mt++)
        #pragma unroll
        for (int nt = 0; nt < NT; nt++)
            #pragma unroll
            for (int i = 0; i < 4; i++) acc[mt][nt][i] = 0.f;

    const int a_m = wr * WROWS + (lane & 7) + ((lane >> 3) & 1) * 8;
    const int a_kq = (lane >> 4) & 1;
    const int b_n = wc * (TN / 2) + (lane & 7) + ((lane >> 4) & 1) * 8;
    const int b_kq = (lane >> 3) & 1;

    load_tiles_h<TM, TN, KCH>(A, lda, Bt, ldb, row0, col0, 0, base, base + (uint32_t)TM * ROWB, tid);
    cp_commit();
    if (NC > 1) {
        load_tiles_h<TM, TN, KCH>(A, lda, Bt, ldb, row0, col0, KCH,
                                  base + STAGE, base + STAGE + (uint32_t)TM * ROWB, tid);
        cp_commit();
    }

    #pragma unroll (NC <= 8 ? NC : 3)
    for (int c = 0; c < NC; c++) {
        if (c + 1 < NC) cp_wait1(); else cp_wait0();
        __syncthreads();
        if (c + 2 < NC) {
            uint32_t a2 = base + (uint32_t)((c + 2) % 3) * STAGE;
            load_tiles_h<TM, TN, KCH>(A, lda, Bt, ldb, row0, col0, (c + 2) * KCH,
                                      a2, a2 + (uint32_t)TM * ROWB, tid);
            cp_commit();
        }
        uint32_t aS = base + (uint32_t)(c % 3) * STAGE, bS = aS + (uint32_t)TM * ROWB;
        #pragma unroll
        for (int kb = 0; kb < CH; kb += 2) {
            uint32_t af[MT][4];
            #pragma unroll
            for (int mt = 0; mt < MT; mt++) {
                int m = a_m + mt * 16;
                int kk = kb + a_kq;
                uint32_t sc = (uint32_t)(((kk ^ m) & 7) | (kk & ~7));
                uint32_t addr = aS + (uint32_t)m * ROWB + (sc << 4);
                LDSM4(af[mt][0], af[mt][1], af[mt][2], af[mt][3], addr);
            }
            uint32_t bf[NT][2];
            #pragma unroll
            for (int p = 0; p < NT / 2; p++) {
                int n = b_n + p * 16;
                int kk = kb + b_kq;
                uint32_t sc = (uint32_t)(((kk ^ n) & 7) | (kk & ~7));
                uint32_t addr = bS + (uint32_t)n * ROWB + (sc << 4);
                LDSM4(bf[2 * p][0], bf[2 * p][1], bf[2 * p + 1][0], bf[2 * p + 1][1], addr);
            }
            #pragma unroll
            for (int mt = 0; mt < MT; mt++)
                #pragma unroll
                for (int nt = 0; nt < NT; nt++)
                    mma16(acc[mt][nt], af[mt], bf[nt]);
        }
    }

    #pragma unroll
    for (int mt = 0; mt < MT; mt++) {
        #pragma unroll
        for (int nt = 0; nt < NT; nt++) {
            int cc = col0 + wc * (TN / 2) + nt * 8 + cq * 2;
            #pragma unroll
            for (int half = 0; half < 2; half++) {
                int r = row0 + wr * WROWS + mt * 16 + g + half * 8;
                float v0 = acc[mt][nt][half * 2];
                float v1 = acc[mt][nt][half * 2 + 1];
                v0 += bias[cc]; v1 += bias[cc + 1];
                if (MODE == 3) {
                    v0 += res[(size_t)r * ldc + cc];
                    v1 += res[(size_t)r * ldc + cc + 1];
                    float2 o; o.x = v0; o.y = v1;
                    *(float2*)(C + (size_t)r * ldc + cc) = o;
                } else if (MODE == 4) {
                    *(__half2*)(C16 + (size_t)r * ldc + cc) =
                        __floats2half2_rn(fmaxf(v0, 0.f), fmaxf(v1, 0.f));
                } else { // MODE 6
                    *(__half2*)(C16 + (size_t)r * ldc + cc) = __floats2half2_rn(v0, v1);
                }
            }
        }
    }
}

// ---------- launch ----------
static inline int smbh(int tm, int tn, int kch) { return 128 + 3 * (tm + tn) * kch * 2; }

extern "C" void kernel_launch(void* const* d_in, const int* in_sizes, int n_in,
                              void* d_out, int out_size)
{
    const float* x      = (const float*)d_in[0];
    const int*   sp     = (const int*)  d_in[1];
    const int*   deg    = (const int*)  d_in[3];
    const float* init_W = (const float*)d_in[4];
    const float* init_b = (const float*)d_in[5];
    const float* cent   = (const float*)d_in[6];
    const float* db     = (const float*)d_in[7];
    const float* vb     = (const float*)d_in[8];
    const float* Wq     = (const float*)d_in[9];
    const float* bq     = (const float*)d_in[10];
    const float* Wk     = (const float*)d_in[11];
    const float* bk     = (const float*)d_in[12];
    const float* Wv     = (const float*)d_in[13];
    const float* bv     = (const float*)d_in[14];
    const float* Wo     = (const float*)d_in[15];
    const float* bo     = (const float*)d_in[16];
    const float* W1     = (const float*)d_in[17];
    const float* b1     = (const float*)d_in[18];
    const float* W2     = (const float*)d_in[19];
    const float* b2     = (const float*)d_in[20];

    float *h, *bqkv;
    __half *hn, *qkv, *attn, *ff, *WqkvT, *WoT, *W1T, *W2T;
    cudaGetSymbolAddress((void**)&h, g_h);
    cudaGetSymbolAddress((void**)&hn, g_hn);
    cudaGetSymbolAddress((void**)&qkv, g_qkv);
    cudaGetSymbolAddress((void**)&attn, g_attn);
    cudaGetSymbolAddress((void**)&ff, g_ff);
    cudaGetSymbolAddress((void**)&WqkvT, g_WqkvT);
    cudaGetSymbolAddress((void**)&bqkv, g_bqkv);
    cudaGetSymbolAddress((void**)&WoT, g_WoT);
    cudaGetSymbolAddress((void**)&W1T, g_W1T);
    cudaGetSymbolAddress((void**)&W2T, g_W2T);

    cudaFuncSetAttribute((const void*)gemm_h<128, 64, 64, 512, 6>,  cudaFuncAttributeMaxDynamicSharedMemorySize, smbh(128, 64, 64));
    cudaFuncSetAttribute((const void*)gemm_h<128, 64, 64, 512, 4>,  cudaFuncAttributeMaxDynamicSharedMemorySize, smbh(128, 64, 64));
    cudaFuncSetAttribute((const void*)gemm_h<64, 64, 64, 512, 6>,   cudaFuncAttributeMaxDynamicSharedMemorySize, smbh(64, 64, 64));
    cudaFuncSetAttribute((const void*)gemm_h<64, 64, 64, 512, 4>,   cudaFuncAttributeMaxDynamicSharedMemorySize, smbh(64, 64, 64));
    cudaFuncSetAttribute((const void*)gemm_h<64, 64, 64, 512, 3>,   cudaFuncAttributeMaxDynamicSharedMemorySize, smbh(64, 64, 64));
    cudaFuncSetAttribute((const void*)gemm_h<64, 64, 64, 2048, 3>,  cudaFuncAttributeMaxDynamicSharedMemorySize, smbh(64, 64, 64));

    // ---- packing (fp16) ----
    fast_pack_qkvT<<<dim3(1, DD / 64, NL * 3 * NH), 256>>>(Wq, Wk, Wv, WqkvT);
    fast_transpose<<<dim3(DD / 64, DD / 64, NL), 256>>>(Wo, WoT, DD, DD);
    fast_transpose<<<dim3(FFD / 64, DD / 64, NL), 256>>>(W1, W1T, DD, FFD);
    fast_transpose<<<dim3(DD / 64, FFD / 64, NL), 256>>>(W2, W2T, FFD, DD);
    pack_bias<<<(NL * QKVW + 255) / 256, 256>>>(bq, bk, bv, bqkv);

    init_h_kernel<<<(NN * DD) / 256, 256>>>(x, init_W, init_b, cent, deg);

    const float scale = 1.f / sqrtf((float)DKH);
    const size_t VOFF  = (size_t)N_ORIG * DD;
    const size_t VOFFQ = (size_t)N_ORIG * QKVW;

    for (int l = 0; l < NL; l++) {
        ln_kernel<<<NN / 8, 256>>>(h, hn);

        if (l < NL - 1) {
            gemm_h<128, 64, 64, 512, 6><<<dim3(QKVW / 64, NN / 128), 256, smbh(128, 64, 64)>>>(
                hn, DD, WqkvT + (size_t)l * QKVW * DD, DD, nullptr, qkv, QKVW,
                bqkv + (size_t)l * QKVW, nullptr);

            attn_fused<<<dim3(NG, NH), 128>>>(qkv, attn, sp, db, vb, scale, 0);

            gemm_h<64, 64, 64, 512, 3><<<dim3(DD / 64, NN / 64), 256, smbh(64, 64, 64)>>>(
                attn, DD, WoT + (size_t)l * DD * DD, DD, h, nullptr, DD,
                bo + (size_t)l * DD, h);

            ln_kernel<<<NN / 8, 256>>>(h, hn);

            gemm_h<128, 64, 64, 512, 4><<<dim3(FFD / 64, NN / 128), 256, smbh(128, 64, 64)>>>(
                hn, DD, W1T + (size_t)l * DD * FFD, DD, nullptr, ff, FFD,
                b1 + (size_t)l * FFD, nullptr);

            gemm_h<64, 64, 64, 2048, 3><<<dim3(DD / 64, NN / 64), 256, smbh(64, 64, 64)>>>(
                ff, FFD, W2T + (size_t)l * FFD * DD, FFD, h, nullptr, DD,
                b2 + (size_t)l * DD, h);
        } else {
            gemm_h<128, 64, 64, 512, 6><<<dim3((QKVW - DD) / 64, NN / 128), 256, smbh(128, 64, 64)>>>(
                hn, DD, WqkvT + (size_t)l * QKVW * DD + (size_t)DD * DD, DD,
                nullptr, qkv + DD, QKVW,
                bqkv + (size_t)l * QKVW + DD, nullptr);
            gemm_h<64, 64, 64, 512, 6><<<dim3(DD / 64, 1), 256, smbh(64, 64, 64)>>>(
                hn + VOFF, DD, WqkvT + (size_t)l * QKVW * DD, DD,
                nullptr, qkv + VOFFQ, QKVW,
                bqkv + (size_t)l * QKVW, nullptr);

            attn_fused<<<dim3(NG, NH), 128>>>(qkv, attn, sp, db, vb, scale, 1);

            gemm_h<64, 64, 64, 512, 3><<<dim3(DD / 64, 1), 256, smbh(64, 64, 64)>>>(
                attn + VOFF, DD, WoT + (size_t)l * DD * DD, DD, h + VOFF, nullptr, DD,
                bo + (size_t)l * DD, h + VOFF);

            ln_kernel<<<NG / 8, 256>>>(h + VOFF, hn + VOFF);

            gemm_h<64, 64, 64, 512, 4><<<dim3(FFD / 64, 1), 256, smbh(64, 64, 64)>>>(
                hn + VOFF, DD, W1T + (size_t)l * DD * FFD, DD, nullptr, ff, FFD,
                b1 + (size_t)l * FFD, nullptr);

            // final FFN2 writes the output tensor directly (64 x 512)
            gemm_h<64, 64, 64, 2048, 3><<<dim3(DD / 64, 1), 256, smbh(64, 64, 64)>>>(
                ff, FFD, W2T + (size_t)l * FFD * DD, FFD, (float*)d_out, nullptr, DD,
                b2 + (size_t)l * DD, h + VOFF);
        }
    }
}

// round 16
// speedup vs baseline: 1.0398x; 1.0398x over previous
#include <cuda_runtime.h>
#include <cuda_fp16.h>
#include <math.h>
#include <stdint.h>

#define NG      64
#define N_ORIG  1984
#define NN      2048
#define DD      512
#define NH      8
#define DKH     64
#define FFD     2048
#define NL      4
#define NFE     32
#define MAX_SP  100
#define MAX_DEG 100
#define QKVW    1536

// ---------- scratch ----------
__device__ float  g_h[NN * DD];
__device__ __half g_hn[NN * DD];
__device__ __half g_qkv[NN * QKVW];
__device__ __half g_attn[NN * DD];
__device__ __half g_ff[(size_t)NN * FFD];
__device__ __half g_WqkvT[NL * QKVW * DD];
__device__ float  g_bqkv[NL * QKVW];
__device__ __half g_WoT[NL * DD * DD];
__device__ __half g_W1T[NL * DD * FFD];
__device__ __half g_W2T[NL * FFD * DD];
__device__ float  g_Bs[NG * 32 * 32];   // per-graph bias blocks (layer-invariant)

// ---------- helpers ----------
__device__ __forceinline__ uint32_t smem_u32(const void* p) {
    uint32_t a;
    asm("{ .reg .u64 t; cvta.to.shared.u64 t, %1; cvt.u32.u64 %0, t; }" : "=r"(a) : "l"(p));
    return a;
}
__device__ __forceinline__ void cp_async16(uint32_t d, const void* g) {
    asm volatile("cp.async.cg.shared.global [%0], [%1], 16;" :: "r"(d), "l"(g));
}
__device__ __forceinline__ void cp_commit() { asm volatile("cp.async.commit_group;" ::: "memory"); }
__device__ __forceinline__ void cp_wait1()  { asm volatile("cp.async.wait_group 1;"  ::: "memory"); }
__device__ __forceinline__ void cp_wait0()  { asm volatile("cp.async.wait_group 0;"  ::: "memory"); }

#define LDSM4(r0, r1, r2, r3, addr) \
    asm volatile("ldmatrix.sync.aligned.m8n8.x4.shared.b16 {%0,%1,%2,%3}, [%4];" \
        : "=r"(r0), "=r"(r1), "=r"(r2), "=r"(r3) : "r"(addr))

__device__ __forceinline__ void mma16(float* c, const uint32_t* a, const uint32_t* b) {
    asm volatile(
        "mma.sync.aligned.m16n8k16.row.col.f32.f16.f16.f32 "
        "{%0,%1,%2,%3}, {%4,%5,%6,%7}, {%8,%9}, {%0,%1,%2,%3};"
        : "+f"(c[0]), "+f"(c[1]), "+f"(c[2]), "+f"(c[3])
        : "r"(a[0]), "r"(a[1]), "r"(a[2]), "r"(a[3]), "r"(b[0]), "r"(b[1]));
}

// ---------- small kernels ----------
__global__ void init_h_kernel(const float* __restrict__ x, const float* __restrict__ W,
                              const float* __restrict__ b, const float* __restrict__ cent,
                              const int* __restrict__ deg)
{
    int idx = blockIdx.x * blockDim.x + threadIdx.x;
    if (idx >= NN * DD) return;
    int n = idx / DD, d = idx % DD;
    float v = 0.f;
    if (n < N_ORIG) {
        v = b[d];
        #pragma unroll
        for (int f = 0; f < NFE; f++) v += x[n * NFE + f] * W[f * DD + d];
    }
    g_h[idx] = v + cent[min(deg[n], MAX_DEG) * DD + d];
}

// precompute per-graph 32x32 bias blocks (layer-invariant)
__global__ void __launch_bounds__(128)
build_Bs(const int* __restrict__ sp, const float* __restrict__ db,
         const float* __restrict__ vb)
{
    const int g = blockIdx.x;
    for (int u = threadIdx.x; u < 1024; u += 128) {
        int rr = u >> 5, cc = u & 31;
        int i = (rr < 31) ? g * 31 + rr : N_ORIG + g;
        int j = (cc < 31) ? g * 31 + cc : N_ORIG + g;
        float bvv;
        if (i == j)                        bvv = db[0];
        else if ((rr == 31) != (cc == 31)) bvv = vb[0];
        else                               bvv = db[min(sp[(size_t)i * N_ORIG + j], MAX_SP)];
        g_Bs[g * 1024 + u] = bvv;
    }
}

// LN; one WARP per row, 8 rows/CTA, fp32 in -> fp16 out
__global__ void __launch_bounds__(256)
ln_kernel(const float* __restrict__ in, __half* __restrict__ out)
{
    const int w = threadIdx.x >> 5, lane = threadIdx.x & 31;
    const int row = blockIdx.x * 8 + w;
    const float* p = in + (size_t)row * DD;
    float4 v[4];
    float a = 0.f, q = 0.f;
    #pragma unroll
    for (int i = 0; i < 4; i++) {
        v[i] = *(const float4*)(p + i * 128 + lane * 4);
        a += v[i].x + v[i].y + v[i].z + v[i].w;
        q += v[i].x * v[i].x + v[i].y * v[i].y + v[i].z * v[i].z + v[i].w * v[i].w;
    }
    #pragma unroll
    for (int o = 16; o; o >>= 1) {
        a += __shfl_xor_sync(~0u, a, o);
        q += __shfl_xor_sync(~0u, q, o);
    }
    float mean = a * (1.f / DD);
    float var  = q * (1.f / DD) - mean * mean;
    float r = rsqrtf(var + 1e-5f);
    __half* o = out + (size_t)row * DD;
    #pragma unroll
    for (int i = 0; i < 4; i++) {
        int j = i * 128 + lane * 4;
        *(__half2*)(o + j)     = __floats2half2_rn((v[i].x - mean) * r, (v[i].y - mean) * r);
        *(__half2*)(o + j + 2) = __floats2half2_rn((v[i].z - mean) * r, (v[i].w - mean) * r);
    }
}

// ---------- fast 64x64 transpose, fp32 -> fp16 (stride 68) ----------
__global__ void __launch_bounds__(256)
fast_transpose(const float* __restrict__ in, __half* __restrict__ out, int R, int C)
{
    __shared__ float t[64][68];
    in  += (size_t)blockIdx.z * R * C;
    out += (size_t)blockIdx.z * R * C;
    const int c0 = blockIdx.x * 64, r0 = blockIdx.y * 64;
    const int tid = threadIdx.x;

    int lr = tid >> 4, lc4 = tid & 15;
    #pragma unroll
    for (int i = 0; i < 4; i++) {
        int r = lr + i * 16;
        float4 v = *(const float4*)(in + (size_t)(r0 + r) * C + c0 + lc4 * 4);
        *(float4*)&t[r][lc4 * 4] = v;
    }
    __syncthreads();

    int c = tid >> 2, s = tid & 3;
    __half* orow = out + (size_t)(c0 + c) * R + r0;
    #pragma unroll
    for (int jj = 0; jj < 8; jj++) {
        int rr = jj * 8 + s * 2;
        *(__half2*)(orow + rr) = __floats2half2_rn(t[rr][c], t[rr + 1][c]);
    }
}

__global__ void __launch_bounds__(256)
fast_pack_qkvT(const float* __restrict__ Wq, const float* __restrict__ Wk,
               const float* __restrict__ Wv, __half* __restrict__ out)
{
    __shared__ float t[64][68];
    int z = blockIdx.z;
    int h = z & 7, qkv = (z >> 3) % 3, l = z / 24;
    const float* src = (qkv == 0 ? Wq : qkv == 1 ? Wk : Wv) + (size_t)(l * NH + h) * DD * DKH;
    __half* dst = out + (size_t)l * QKVW * DD + (size_t)(qkv * DD + h * DKH) * DD;
    const int r0 = blockIdx.y * 64;
    const int tid = threadIdx.x;

    int lr = tid >> 4, lc4 = tid & 15;
    #pragma unroll
    for (int i = 0; i < 4; i++) {
        int r = lr + i * 16;
        float4 v = *(const float4*)(src + (size_t)(r0 + r) * DKH + lc4 * 4);
        *(float4*)&t[r][lc4 * 4] = v;
    }
    __syncthreads();

    int c = tid >> 2, s = tid & 3;
    __half* orow = dst + (size_t)c * DD + r0;
    #pragma unroll
    for (int jj = 0; jj < 8; jj++) {
        int rr = jj * 8 + s * 2;
        *(__half2*)(orow + rr) = __floats2half2_rn(t[rr][c], t[rr + 1][c]);
    }
}

__global__ void pack_bias(const float* __restrict__ bq, const float* __restrict__ bk,
                          const float* __restrict__ bv, float* __restrict__ out)
{
    int idx = blockIdx.x * blockDim.x + threadIdx.x;
    if (idx >= NL * QKVW) return;
    int l = idx / QKVW, p = idx % QKVW;
    float v;
    if (p < DD)            v = bq[l * DD + p];
    else if (p < 2 * DD)   v = bk[l * DD + p - DD];
    else                   v = bv[l * DD + p - 2 * DD];
    out[idx] = v;
}

// ---------- fused block-diagonal attention (precomputed Bs) ----------
__global__ void __launch_bounds__(128)
attn_fused(const __half* __restrict__ qkv, __half* __restrict__ O,
           float scale, int only_virt)
{
    __shared__ float Ks[32][68];
    __shared__ float Vs[32][68];
    __shared__ float Bs[32][33];
    __shared__ float Ps[32][33];

    const int g = blockIdx.x, h = blockIdx.y;
    const int t = threadIdx.x;
    const int r = t >> 2, q4 = t & 3;

    // coalesced Bs fill (float4)
    {
        const float4* src = (const float4*)(g_Bs + g * 1024);
        #pragma unroll
        for (int i = 0; i < 2; i++) {
            int u = (t + i * 128) * 4;
            float4 v = src[t + i * 128];
            int rr = u >> 5, cc = u & 31;
            Bs[rr][cc]     = v.x;
            Bs[rr][cc + 1] = v.y;
            Bs[rr][cc + 2] = v.z;
            Bs[rr][cc + 3] = v.w;
        }
    }

    {
        int n = (r < 31) ? g * 31 + r : N_ORIG + g;
        int d0 = q4 * 16;
        const __half2* kp = (const __half2*)(qkv + (size_t)n * QKVW + DD + h * DKH + d0);
        const __half2* vp = (const __half2*)(qkv + (size_t)n * QKVW + 2 * DD + h * DKH + d0);
        #pragma unroll
        for (int i = 0; i < 8; i++) {
            float2 kf = __half22float2(kp[i]);
            Ks[r][d0 + 2 * i] = kf.x; Ks[r][d0 + 2 * i + 1] = kf.y;
            float2 vf = __half22float2(vp[i]);
            Vs[r][d0 + 2 * i] = vf.x; Vs[r][d0 + 2 * i + 1] = vf.y;
        }
    }
    __syncthreads();

    {
        int nr = (r < 31) ? g * 31 + r : N_ORIG + g;
        const __half2* qp = (const __half2*)(qkv + (size_t)nr * QKVW + h * DKH);
        float2 qv[32];
        #pragma unroll
        for (int i = 0; i < 32; i++) qv[i] = __half22float2(qp[i]);

        float s[8];
        #pragma unroll
        for (int cc = 0; cc < 8; cc++) {
            int c = q4 + 4 * cc;
            const float2* kr = (const float2*)&Ks[c][0];
            float acc = 0.f;
            #pragma unroll
            for (int i = 0; i < 32; i++) {
                float2 k2 = kr[i];
                acc += qv[i].x * k2.x + qv[i].y * k2.y;
            }
            s[cc] = acc * scale + Bs[r][c];
        }
        float m = s[0];
        #pragma unroll
        for (int cc = 1; cc < 8; cc++) m = fmaxf(m, s[cc]);
        m = fmaxf(m, __shfl_xor_sync(~0u, m, 1));
        m = fmaxf(m, __shfl_xor_sync(~0u, m, 2));
        float sum = 0.f;
        #pragma unroll
        for (int cc = 0; cc < 8; cc++) { s[cc] = __expf(s[cc] - m); sum += s[cc]; }
        sum += __shfl_xor_sync(~0u, sum, 1);
        sum += __shfl_xor_sync(~0u, sum, 2);
        float inv = 1.f / sum;
        #pragma unroll
        for (int cc = 0; cc < 8; cc++) Ps[r][q4 + 4 * cc] = s[cc] * inv;
    }
    __syncthreads();

    if (!only_virt || r == 31) {
        float acc[16];
        #pragma unroll
        for (int i = 0; i < 16; i++) acc[i] = 0.f;
        #pragma unroll
        for (int c = 0; c < 32; c++) {
            float p = Ps[r][c];
            #pragma unroll
            for (int i = 0; i < 8; i++) {
                float2 v2 = *(const float2*)&Vs[c][8 * i + 2 * q4];
                acc[2 * i]     += p * v2.x;
                acc[2 * i + 1] += p * v2.y;
            }
        }
        int n = (r < 31) ? g * 31 + r : N_ORIG + g;
        __half* op = O + (size_t)n * DD + h * DKH;
        #pragma unroll
        for (int i = 0; i < 8; i++)
            *(__half2*)(op + 8 * i + 2 * q4) = __floats2half2_rn(acc[2 * i], acc[2 * i + 1]);
    }
}

// ---------- staging: rows of KCH fp16, chunk-swizzled ----------
template<int TM, int TN, int KCH>
__device__ __forceinline__ void load_tiles_h(const __half* A, int lda, const __half* Bt, int ldb,
        int row0, int col0, int k0, uint32_t aS, uint32_t bS, int tid)
{
    constexpr int CH = KCH / 8;
    constexpr int ROWB = KCH * 2;
    #pragma unroll
    for (int i = 0; i < TM * CH / 256; i++) {
        int u = tid + i * 256;
        int r = u / CH, c = u % CH;
        uint32_t sc = (uint32_t)((((c ^ r) & 7) | (c & ~7)));
        cp_async16(aS + (uint32_t)r * ROWB + (sc << 4),
                   A + (size_t)(row0 + r) * lda + k0 + c * 8);
    }
    #pragma unroll
    for (int i = 0; i < TN * CH / 256; i++) {
        int u = tid + i * 256;
        int r = u / CH, c = u % CH;
        uint32_t sc = (uint32_t)((((c ^ r) & 7) | (c & ~7)));
        cp_async16(bS + (uint32_t)r * ROWB + (sc << 4),
                   Bt + (size_t)(col0 + r) * ldb + k0 + c * 8);
    }
}

// ---------- fp16 mma m16n8k16 NT GEMM, compile-time K, occ 2 (R14 config) ----------
// MODE 3: C=fp32 +bias+res | 4: C16=fp16 relu(+bias) | 6: C16=fp16 +bias
template<int TM, int TN, int KCH, int KTOT, int MODE>
__global__ void __launch_bounds__(256, 2)
gemm_h(const __half* __restrict__ A, int lda,
       const __half* __restrict__ Bt, int ldb,
       float* __restrict__ C, __half* __restrict__ C16, int ldc,
       const float* __restrict__ bias,
       const float* __restrict__ res)
{
    constexpr int WROWS = TM / 4;
    constexpr int MT = WROWS / 16;
    constexpr int NT = TN / 16;
    constexpr int CH = KCH / 8;
    constexpr int NC = KTOT / KCH;
    constexpr uint32_t ROWB = (uint32_t)KCH * 2u;
    constexpr uint32_t STAGE = (uint32_t)(TM + TN) * ROWB;

    extern __shared__ char smraw[];
    uint32_t rawu = smem_u32(smraw);
    uint32_t base = (rawu + 127u) & ~127u;

    const int tid = threadIdx.x;
    const int col0 = blockIdx.x * TN;
    const int row0 = blockIdx.y * TM;

    const int w = tid >> 5, lane = tid & 31;
    const int wr = w >> 1, wc = w & 1;
    const int g = lane >> 2, cq = lane & 3;

    float acc[MT][NT][4];
    #pragma unroll
    for (int mt = 0; mt < MT; mt++)
        #pragma unroll
        for (int nt = 0; nt < NT; nt++)
            #pragma unroll
            for (int i = 0; i < 4; i++) acc[mt][nt][i] = 0.f;

    const int a_m = wr * WROWS + (lane & 7) + ((lane >> 3) & 1) * 8;
    const int a_kq = (lane >> 4) & 1;
    const int b_n = wc * (TN / 2) + (lane & 7) + ((lane >> 4) & 1) * 8;
    const int b_kq = (lane >> 3) & 1;

    load_tiles_h<TM, TN, KCH>(A, lda, Bt, ldb, row0, col0, 0, base, base + (uint32_t)TM * ROWB, tid);
    cp_commit();
    if (NC > 1) {
        load_tiles_h<TM, TN, KCH>(A, lda, Bt, ldb, row0, col0, KCH,
                                  base + STAGE, base + STAGE + (uint32_t)TM * ROWB, tid);
        cp_commit();
    }

    #pragma unroll
    for (int c = 0; c < NC; c++) {
        if (c + 1 < NC) cp_wait1(); else cp_wait0();
        __syncthreads();
        if (c + 2 < NC) {
            uint32_t a2 = base + (uint32_t)((c + 2) % 3) * STAGE;
            load_tiles_h<TM, TN, KCH>(A, lda, Bt, ldb, row0, col0, (c + 2) * KCH,
                                      a2, a2 + (uint32_t)TM * ROWB, tid);
            cp_commit();
        }
        uint32_t aS = base + (uint32_t)(c % 3) * STAGE, bS = aS + (uint32_t)TM * ROWB;
        #pragma unroll
        for (int kb = 0; kb < CH; kb += 2) {
            uint32_t af[MT][4];
            #pragma unroll
            for (int mt = 0; mt < MT; mt++) {
                int m = a_m + mt * 16;
                int kk = kb + a_kq;
                uint32_t sc = (uint32_t)(((kk ^ m) & 7) | (kk & ~7));
                uint32_t addr = aS + (uint32_t)m * ROWB + (sc << 4);
                LDSM4(af[mt][0], af[mt][1], af[mt][2], af[mt][3], addr);
            }
            uint32_t bf[NT][2];
            #pragma unroll
            for (int p = 0; p < NT / 2; p++) {
                int n = b_n + p * 16;
                int kk = kb + b_kq;
                uint32_t sc = (uint32_t)(((kk ^ n) & 7) | (kk & ~7));
                uint32_t addr = bS + (uint32_t)n * ROWB + (sc << 4);
                LDSM4(bf[2 * p][0], bf[2 * p][1], bf[2 * p + 1][0], bf[2 * p + 1][1], addr);
            }
            #pragma unroll
            for (int mt = 0; mt < MT; mt++)
                #pragma unroll
                for (int nt = 0; nt < NT; nt++)
                    mma16(acc[mt][nt], af[mt], bf[nt]);
        }
    }

    #pragma unroll
    for (int mt = 0; mt < MT; mt++) {
        #pragma unroll
        for (int nt = 0; nt < NT; nt++) {
            int cc = col0 + wc * (TN / 2) + nt * 8 + cq * 2;
            #pragma unroll
            for (int half = 0; half < 2; half++) {
                int r = row0 + wr * WROWS + mt * 16 + g + half * 8;
                float v0 = acc[mt][nt][half * 2];
                float v1 = acc[mt][nt][half * 2 + 1];
                v0 += bias[cc]; v1 += bias[cc + 1];
                if (MODE == 3) {
                    v0 += res[(size_t)r * ldc + cc];
                    v1 += res[(size_t)r * ldc + cc + 1];
                    float2 o; o.x = v0; o.y = v1;
                    *(float2*)(C + (size_t)r * ldc + cc) = o;
                } else if (MODE == 4) {
                    *(__half2*)(C16 + (size_t)r * ldc + cc) =
                        __floats2half2_rn(fmaxf(v0, 0.f), fmaxf(v1, 0.f));
                } else { // MODE 6
                    *(__half2*)(C16 + (size_t)r * ldc + cc) = __floats2half2_rn(v0, v1);
                }
            }
        }
    }
}

// ---------- launch ----------
static inline int smbh(int tm, int tn, int kch) { return 128 + 3 * (tm + tn) * kch * 2; }

extern "C" void kernel_launch(void* const* d_in, const int* in_sizes, int n_in,
                              void* d_out, int out_size)
{
    const float* x      = (const float*)d_in[0];
    const int*   sp     = (const int*)  d_in[1];
    const int*   deg    = (const int*)  d_in[3];
    const float* init_W = (const float*)d_in[4];
    const float* init_b = (const float*)d_in[5];
    const float* cent   = (const float*)d_in[6];
    const float* db     = (const float*)d_in[7];
    const float* vb     = (const float*)d_in[8];
    const float* Wq     = (const float*)d_in[9];
    const float* bq     = (const float*)d_in[10];
    const float* Wk     = (const float*)d_in[11];
    const float* bk     = (const float*)d_in[12];
    const float* Wv     = (const float*)d_in[13];
    const float* bv     = (const float*)d_in[14];
    const float* Wo     = (const float*)d_in[15];
    const float* bo     = (const float*)d_in[16];
    const float* W1     = (const float*)d_in[17];
    const float* b1     = (const float*)d_in[18];
    const float* W2     = (const float*)d_in[19];
    const float* b2     = (const float*)d_in[20];

    float *h, *bqkv;
    __half *hn, *qkv, *attn, *ff, *WqkvT, *WoT, *W1T, *W2T;
    cudaGetSymbolAddress((void**)&h, g_h);
    cudaGetSymbolAddress((void**)&hn, g_hn);
    cudaGetSymbolAddress((void**)&qkv, g_qkv);
    cudaGetSymbolAddress((void**)&attn, g_attn);
    cudaGetSymbolAddress((void**)&ff, g_ff);
    cudaGetSymbolAddress((void**)&WqkvT, g_WqkvT);
    cudaGetSymbolAddress((void**)&bqkv, g_bqkv);
    cudaGetSymbolAddress((void**)&WoT, g_WoT);
    cudaGetSymbolAddress((void**)&W1T, g_W1T);
    cudaGetSymbolAddress((void**)&W2T, g_W2T);

    cudaFuncSetAttribute((const void*)gemm_h<128, 128, 64, 512, 6>,   cudaFuncAttributeMaxDynamicSharedMemorySize, smbh(128, 128, 64));
    cudaFuncSetAttribute((const void*)gemm_h<128, 128, 64, 512, 4>,   cudaFuncAttributeMaxDynamicSharedMemorySize, smbh(128, 128, 64));
    cudaFuncSetAttribute((const void*)gemm_h<64, 64, 128, 512, 6>,    cudaFuncAttributeMaxDynamicSharedMemorySize, smbh(64, 64, 128));
    cudaFuncSetAttribute((const void*)gemm_h<64, 64, 128, 512, 4>,    cudaFuncAttributeMaxDynamicSharedMemorySize, smbh(64, 64, 128));
    cudaFuncSetAttribute((const void*)gemm_h<64, 64, 128, 512, 3>,    cudaFuncAttributeMaxDynamicSharedMemorySize, smbh(64, 64, 128));
    cudaFuncSetAttribute((const void*)gemm_h<64, 64, 128, 2048, 3>,   cudaFuncAttributeMaxDynamicSharedMemorySize, smbh(64, 64, 128));

    // ---- packing (fp16) + bias block precompute ----
    fast_pack_qkvT<<<dim3(1, DD / 64, NL * 3 * NH), 256>>>(Wq, Wk, Wv, WqkvT);
    fast_transpose<<<dim3(DD / 64, DD / 64, NL), 256>>>(Wo, WoT, DD, DD);
    fast_transpose<<<dim3(FFD / 64, DD / 64, NL), 256>>>(W1, W1T, DD, FFD);
    fast_transpose<<<dim3(DD / 64, FFD / 64, NL), 256>>>(W2, W2T, FFD, DD);
    pack_bias<<<(NL * QKVW + 255) / 256, 256>>>(bq, bk, bv, bqkv);
    build_Bs<<<NG, 128>>>(sp, db, vb);

    init_h_kernel<<<(NN * DD) / 256, 256>>>(x, init_W, init_b, cent, deg);

    const float scale = 1.f / sqrtf((float)DKH);
    const size_t VOFF  = (size_t)N_ORIG * DD;
    const size_t VOFFQ = (size_t)N_ORIG * QKVW;

    for (int l = 0; l < NL; l++) {
        ln_kernel<<<NN / 8, 256>>>(h, hn);

        if (l < NL - 1) {
            gemm_h<128, 128, 64, 512, 6><<<dim3(QKVW / 128, NN / 128), 256, smbh(128, 128, 64)>>>(
                hn, DD, WqkvT + (size_t)l * QKVW * DD, DD, nullptr, qkv, QKVW,
                bqkv + (size_t)l * QKVW, nullptr);

            attn_fused<<<dim3(NG, NH), 128>>>(qkv, attn, scale, 0);

            gemm_h<64, 64, 128, 512, 3><<<dim3(DD / 64, NN / 64), 256, smbh(64, 64, 128)>>>(
                attn, DD, WoT + (size_t)l * DD * DD, DD, h, nullptr, DD,
                bo + (size_t)l * DD, h);

            ln_kernel<<<NN / 8, 256>>>(h, hn);

            gemm_h<128, 128, 64, 512, 4><<<dim3(FFD / 128, NN / 128), 256, smbh(128, 128, 64)>>>(
                hn, DD, W1T + (size_t)l * DD * FFD, DD, nullptr, ff, FFD,
                b1 + (size_t)l * FFD, nullptr);

            gemm_h<64, 64, 128, 2048, 3><<<dim3(DD / 64, NN / 64), 256, smbh(64, 64, 128)>>>(
                ff, FFD, W2T + (size_t)l * FFD * DD, FFD, h, nullptr, DD,
                b2 + (size_t)l * DD, h);
        } else {
            gemm_h<128, 128, 64, 512, 6><<<dim3((QKVW - DD) / 128, NN / 128), 256, smbh(128, 128, 64)>>>(
                hn, DD, WqkvT + (size_t)l * QKVW * DD + (size_t)DD * DD, DD,
                nullptr, qkv + DD, QKVW,
                bqkv + (size_t)l * QKVW + DD, nullptr);
            gemm_h<64, 64, 128, 512, 6><<<dim3(DD / 64, 1), 256, smbh(64, 64, 128)>>>(
                hn + VOFF, DD, WqkvT + (size_t)l * QKVW * DD, DD,
                nullptr, qkv + VOFFQ, QKVW,
                bqkv + (size_t)l * QKVW, nullptr);

            attn_fused<<<dim3(NG, NH), 128>>>(qkv, attn, scale, 1);

            gemm_h<64, 64, 128, 512, 3><<<dim3(DD / 64, 1), 256, smbh(64, 64, 128)>>>(
                attn + VOFF, DD, WoT + (size_t)l * DD * DD, DD, h + VOFF, nullptr, DD,
                bo + (size_t)l * DD, h + VOFF);

            ln_kernel<<<NG / 8, 256>>>(h + VOFF, hn + VOFF);

            gemm_h<64, 64, 128, 512, 4><<<dim3(FFD / 64, 1), 256, smbh(64, 64, 128)>>>(
                hn + VOFF, DD, W1T + (size_t)l * DD * FFD, DD, nullptr, ff, FFD,
                b1 + (size_t)l * FFD, nullptr);

            // final FFN2 writes the output tensor directly (64 x 512)
            gemm_h<64, 64, 128, 2048, 3><<<dim3(DD / 64, 1), 256, smbh(64, 64, 128)>>>(
                ff, FFD, W2T + (size_t)l * FFD * DD, FFD, (float*)d_out, nullptr, DD,
                b2 + (size_t)l * DD, h + VOFF);
        }
    }
}

// round 17
// speedup vs baseline: 1.0534x; 1.0131x over previous
#include <cuda_runtime.h>
#include <cuda_fp16.h>
#include <math.h>
#include <stdint.h>

#define NG      64
#define N_ORIG  1984
#define NN      2048
#define DD      512
#define NH      8
#define DKH     64
#define FFD     2048
#define NL      4
#define NFE     32
#define MAX_SP  100
#define MAX_DEG 100
#define QKVW    1536

// ---------- scratch ----------
__device__ float  g_h[NN * DD];
__device__ __half g_hn[NN * DD];
__device__ __half g_qkv[NN * QKVW];
__device__ __half g_attn[NN * DD];
__device__ __half g_ff[(size_t)NN * FFD];
__device__ __half g_WqkvT[NL * QKVW * DD];
__device__ float  g_bqkv[NL * QKVW];
__device__ __half g_WoT[NL * DD * DD];
__device__ __half g_W1T[NL * DD * FFD];
__device__ __half g_W2T[NL * FFD * DD];
__device__ float  g_Bs[NG * 32 * 32];
__device__ float  g_part[4 * NG * DD];   // split-K partials for last FFN2

// ---------- helpers ----------
__device__ __forceinline__ uint32_t smem_u32(const void* p) {
    uint32_t a;
    asm("{ .reg .u64 t; cvta.to.shared.u64 t, %1; cvt.u32.u64 %0, t; }" : "=r"(a) : "l"(p));
    return a;
}
__device__ __forceinline__ void cp_async16(uint32_t d, const void* g) {
    asm volatile("cp.async.cg.shared.global [%0], [%1], 16;" :: "r"(d), "l"(g));
}
__device__ __forceinline__ void cp_commit() { asm volatile("cp.async.commit_group;" ::: "memory"); }
__device__ __forceinline__ void cp_wait1()  { asm volatile("cp.async.wait_group 1;"  ::: "memory"); }
__device__ __forceinline__ void cp_wait0()  { asm volatile("cp.async.wait_group 0;"  ::: "memory"); }

#define LDSM4(r0, r1, r2, r3, addr) \
    asm volatile("ldmatrix.sync.aligned.m8n8.x4.shared.b16 {%0,%1,%2,%3}, [%4];" \
        : "=r"(r0), "=r"(r1), "=r"(r2), "=r"(r3) : "r"(addr))

__device__ __forceinline__ void mma16(float* c, const uint32_t* a, const uint32_t* b) {
    asm volatile(
        "mma.sync.aligned.m16n8k16.row.col.f32.f16.f16.f32 "
        "{%0,%1,%2,%3}, {%4,%5,%6,%7}, {%8,%9}, {%0,%1,%2,%3};"
        : "+f"(c[0]), "+f"(c[1]), "+f"(c[2]), "+f"(c[3])
        : "r"(a[0]), "r"(a[1]), "r"(a[2]), "r"(a[3]), "r"(b[0]), "r"(b[1]));
}

// ---------- small kernels ----------
__global__ void init_h_kernel(const float* __restrict__ x, const float* __restrict__ W,
                              const float* __restrict__ b, const float* __restrict__ cent,
                              const int* __restrict__ deg)
{
    int idx = blockIdx.x * blockDim.x + threadIdx.x;
    if (idx >= NN * DD) return;
    int n = idx / DD, d = idx % DD;
    float v = 0.f;
    if (n < N_ORIG) {
        v = b[d];
        #pragma unroll
        for (int f = 0; f < NFE; f++) v += x[n * NFE + f] * W[f * DD + d];
    }
    g_h[idx] = v + cent[min(deg[n], MAX_DEG) * DD + d];
}

__global__ void __launch_bounds__(128)
build_Bs(const int* __restrict__ sp, const float* __restrict__ db,
         const float* __restrict__ vb)
{
    const int g = blockIdx.x;
    for (int u = threadIdx.x; u < 1024; u += 128) {
        int rr = u >> 5, cc = u & 31;
        int i = (rr < 31) ? g * 31 + rr : N_ORIG + g;
        int j = (cc < 31) ? g * 31 + cc : N_ORIG + g;
        float bvv;
        if (i == j)                        bvv = db[0];
        else if ((rr == 31) != (cc == 31)) bvv = vb[0];
        else                               bvv = db[min(sp[(size_t)i * N_ORIG + j], MAX_SP)];
        g_Bs[g * 1024 + u] = bvv;
    }
}

// LN; one WARP per row, 8 rows/CTA
__global__ void __launch_bounds__(256)
ln_kernel(const float* __restrict__ in, __half* __restrict__ out)
{
    const int w = threadIdx.x >> 5, lane = threadIdx.x & 31;
    const int row = blockIdx.x * 8 + w;
    const float* p = in + (size_t)row * DD;
    float4 v[4];
    float a = 0.f, q = 0.f;
    #pragma unroll
    for (int i = 0; i < 4; i++) {
        v[i] = *(const float4*)(p + i * 128 + lane * 4);
        a += v[i].x + v[i].y + v[i].z + v[i].w;
        q += v[i].x * v[i].x + v[i].y * v[i].y + v[i].z * v[i].z + v[i].w * v[i].w;
    }
    #pragma unroll
    for (int o = 16; o; o >>= 1) {
        a += __shfl_xor_sync(~0u, a, o);
        q += __shfl_xor_sync(~0u, q, o);
    }
    float mean = a * (1.f / DD);
    float var  = q * (1.f / DD) - mean * mean;
    float r = rsqrtf(var + 1e-5f);
    __half* o = out + (size_t)row * DD;
    #pragma unroll
    for (int i = 0; i < 4; i++) {
        int j = i * 128 + lane * 4;
        *(__half2*)(o + j)     = __floats2half2_rn((v[i].x - mean) * r, (v[i].y - mean) * r);
        *(__half2*)(o + j + 2) = __floats2half2_rn((v[i].z - mean) * r, (v[i].w - mean) * r);
    }
}

// ---------- fast 64x64 transpose, fp32 -> fp16, full-sector stores ----------
__global__ void __launch_bounds__(256)
fast_transpose(const float* __restrict__ in, __half* __restrict__ out, int R, int C)
{
    __shared__ float t[64][68];
    in  += (size_t)blockIdx.z * R * C;
    out += (size_t)blockIdx.z * R * C;
    const int c0 = blockIdx.x * 64, r0 = blockIdx.y * 64;
    const int tid = threadIdx.x;

    int lr = tid >> 4, lc4 = tid & 15;
    #pragma unroll
    for (int i = 0; i < 4; i++) {
        int r = lr + i * 16;
        float4 v = *(const float4*)(in + (size_t)(r0 + r) * C + c0 + lc4 * 4);
        *(float4*)&t[r][lc4 * 4] = v;
    }
    __syncthreads();

    // 8 threads per output row, full 32B sectors
    int c = tid >> 3, e = tid & 7;
    #pragma unroll
    for (int pass = 0; pass < 2; pass++) {
        int cc = c + pass * 32;
        __half* orow = out + (size_t)(c0 + cc) * R + r0;
        #pragma unroll
        for (int j = 0; j < 4; j++) {
            int rr = j * 16 + e * 2;
            *(__half2*)(orow + rr) = __floats2half2_rn(t[rr][cc], t[rr + 1][cc]);
        }
    }
}

__global__ void __launch_bounds__(256)
fast_pack_qkvT(const float* __restrict__ Wq, const float* __restrict__ Wk,
               const float* __restrict__ Wv, __half* __restrict__ out)
{
    __shared__ float t[64][68];
    int z = blockIdx.z;
    int h = z & 7, qkv = (z >> 3) % 3, l = z / 24;
    const float* src = (qkv == 0 ? Wq : qkv == 1 ? Wk : Wv) + (size_t)(l * NH + h) * DD * DKH;
    __half* dst = out + (size_t)l * QKVW * DD + (size_t)(qkv * DD + h * DKH) * DD;
    const int r0 = blockIdx.y * 64;
    const int tid = threadIdx.x;

    int lr = tid >> 4, lc4 = tid & 15;
    #pragma unroll
    for (int i = 0; i < 4; i++) {
        int r = lr + i * 16;
        float4 v = *(const float4*)(src + (size_t)(r0 + r) * DKH + lc4 * 4);
        *(float4*)&t[r][lc4 * 4] = v;
    }
    __syncthreads();

    int c = tid >> 3, e = tid & 7;
    #pragma unroll
    for (int pass = 0; pass < 2; pass++) {
        int cc = c + pass * 32;
        __half* orow = dst + (size_t)cc * DD + r0;
        #pragma unroll
        for (int j = 0; j < 4; j++) {
            int rr = j * 16 + e * 2;
            *(__half2*)(orow + rr) = __floats2half2_rn(t[rr][cc], t[rr + 1][cc]);
        }
    }
}

__global__ void pack_bias(const float* __restrict__ bq, const float* __restrict__ bk,
                          const float* __restrict__ bv, float* __restrict__ out)
{
    int idx = blockIdx.x * blockDim.x + threadIdx.x;
    if (idx >= NL * QKVW) return;
    int l = idx / QKVW, p = idx % QKVW;
    float v;
    if (p < DD)            v = bq[l * DD + p];
    else if (p < 2 * DD)   v = bk[l * DD + p - DD];
    else                   v = bv[l * DD + p - 2 * DD];
    out[idx] = v;
}

// reduce split-K partials: out = sum_z part[z] + b2 + h_res
__global__ void reduce_out(const float* __restrict__ b2l, float* __restrict__ out)
{
    int i = blockIdx.x * 256 + threadIdx.x;   // NG*DD = 32768
    float v = g_part[i] + g_part[NG * DD + i] + g_part[2 * NG * DD + i] + g_part[3 * NG * DD + i];
    out[i] = v + b2l[i & (DD - 1)] + g_h[(size_t)N_ORIG * DD + i];
}

// ---------- fused block-diagonal attention (precomputed Bs) ----------
__global__ void __launch_bounds__(128)
attn_fused(const __half* __restrict__ qkv, __half* __restrict__ O,
           float scale, int only_virt)
{
    __shared__ float Ks[32][68];
    __shared__ float Vs[32][68];
    __shared__ float Bs[32][33];
    __shared__ float Ps[32][33];

    const int g = blockIdx.x, h = blockIdx.y;
    const int t = threadIdx.x;
    const int r = t >> 2, q4 = t & 3;

    {
        const float4* src = (const float4*)(g_Bs + g * 1024);
        #pragma unroll
        for (int i = 0; i < 2; i++) {
            int u = (t + i * 128) * 4;
            float4 v = src[t + i * 128];
            int rr = u >> 5, cc = u & 31;
            Bs[rr][cc]     = v.x;
            Bs[rr][cc + 1] = v.y;
            Bs[rr][cc + 2] = v.z;
            Bs[rr][cc + 3] = v.w;
        }
    }

    {
        int n = (r < 31) ? g * 31 + r : N_ORIG + g;
        int d0 = q4 * 16;
        const __half2* kp = (const __half2*)(qkv + (size_t)n * QKVW + DD + h * DKH + d0);
        const __half2* vp = (const __half2*)(qkv + (size_t)n * QKVW + 2 * DD + h * DKH + d0);
        #pragma unroll
        for (int i = 0; i < 8; i++) {
            float2 kf = __half22float2(kp[i]);
            Ks[r][d0 + 2 * i] = kf.x; Ks[r][d0 + 2 * i + 1] = kf.y;
            float2 vf = __half22float2(vp[i]);
            Vs[r][d0 + 2 * i] = vf.x; Vs[r][d0 + 2 * i + 1] = vf.y;
        }
    }
    __syncthreads();

    {
        int nr = (r < 31) ? g * 31 + r : N_ORIG + g;
        const __half2* qp = (const __half2*)(qkv + (size_t)nr * QKVW + h * DKH);
        float2 qv[32];
        #pragma unroll
        for (int i = 0; i < 32; i++) qv[i] = __half22float2(qp[i]);

        float s[8];
        #pragma unroll
        for (int cc = 0; cc < 8; cc++) {
            int c = q4 + 4 * cc;
            const float2* kr = (const float2*)&Ks[c][0];
            float acc = 0.f;
            #pragma unroll
            for (int i = 0; i < 32; i++) {
                float2 k2 = kr[i];
                acc += qv[i].x * k2.x + qv[i].y * k2.y;
            }
            s[cc] = acc * scale + Bs[r][c];
        }
        float m = s[0];
        #pragma unroll
        for (int cc = 1; cc < 8; cc++) m = fmaxf(m, s[cc]);
        m = fmaxf(m, __shfl_xor_sync(~0u, m, 1));
        m = fmaxf(m, __shfl_xor_sync(~0u, m, 2));
        float sum = 0.f;
        #pragma unroll
        for (int cc = 0; cc < 8; cc++) { s[cc] = __expf(s[cc] - m); sum += s[cc]; }
        sum += __shfl_xor_sync(~0u, sum, 1);
        sum += __shfl_xor_sync(~0u, sum, 2);
        float inv = 1.f / sum;
        #pragma unroll
        for (int cc = 0; cc < 8; cc++) Ps[r][q4 + 4 * cc] = s[cc] * inv;
    }
    __syncthreads();

    if (!only_virt || r == 31) {
        float acc[16];
        #pragma unroll
        for (int i = 0; i < 16; i++) acc[i] = 0.f;
        #pragma unroll
        for (int c = 0; c < 32; c++) {
            float p = Ps[r][c];
            #pragma unroll
            for (int i = 0; i < 8; i++) {
                float2 v2 = *(const float2*)&Vs[c][8 * i + 2 * q4];
                acc[2 * i]     += p * v2.x;
                acc[2 * i + 1] += p * v2.y;
            }
        }
        int n = (r < 31) ? g * 31 + r : N_ORIG + g;
        __half* op = O + (size_t)n * DD + h * DKH;
        #pragma unroll
        for (int i = 0; i < 8; i++)
            *(__half2*)(op + 8 * i + 2 * q4) = __floats2half2_rn(acc[2 * i], acc[2 * i + 1]);
    }
}

// ---------- staging: rows of KCH fp16, chunk-swizzled ----------
template<int TM, int TN, int KCH>
__device__ __forceinline__ void load_tiles_h(const __half* A, int lda, const __half* Bt, int ldb,
        int row0, int col0, int k0, uint32_t aS, uint32_t bS, int tid)
{
    constexpr int CH = KCH / 8;
    constexpr int ROWB = KCH * 2;
    #pragma unroll
    for (int i = 0; i < TM * CH / 256; i++) {
        int u = tid + i * 256;
        int r = u / CH, c = u % CH;
        uint32_t sc = (uint32_t)((((c ^ r) & 7) | (c & ~7)));
        cp_async16(aS + (uint32_t)r * ROWB + (sc << 4),
                   A + (size_t)(row0 + r) * lda + k0 + c * 8);
    }
    #pragma unroll
    for (int i = 0; i < TN * CH / 256; i++) {
        int u = tid + i * 256;
        int r = u / CH, c = u % CH;
        uint32_t sc = (uint32_t)((((c ^ r) & 7) | (c & ~7)));
        cp_async16(bS + (uint32_t)r * ROWB + (sc << 4),
                   Bt + (size_t)(col0 + r) * ldb + k0 + c * 8);
    }
}

// ---------- fp16 mma m16n8k16 NT GEMM, compile-time K, occ 2 ----------
// MODE 3: C=fp32 +bias+res | 4: C16=fp16 relu(+bias) | 6: C16=fp16 +bias
// MODE 8: split-K: blockIdx.z selects K-slice; C = raw partial (no bias), offset z*NG*DD
template<int TM, int TN, int KCH, int KTOT, int MODE>
__global__ void __launch_bounds__(256, 2)
gemm_h(const __half* __restrict__ A, int lda,
       const __half* __restrict__ Bt, int ldb,
       float* __restrict__ C, __half* __restrict__ C16, int ldc,
       const float* __restrict__ bias,
       const float* __restrict__ res)
{
    constexpr int WROWS = TM / 4;
    constexpr int MT = WROWS / 16;
    constexpr int NT = TN / 16;
    constexpr int CH = KCH / 8;
    constexpr int NC = KTOT / KCH;
    constexpr uint32_t ROWB = (uint32_t)KCH * 2u;
    constexpr uint32_t STAGE = (uint32_t)(TM + TN) * ROWB;

    extern __shared__ char smraw[];
    uint32_t rawu = smem_u32(smraw);
    uint32_t base = (rawu + 127u) & ~127u;

    const int tid = threadIdx.x;
    const int col0 = blockIdx.x * TN;
    const int row0 = blockIdx.y * TM;

    if (MODE == 8) {
        A  += (size_t)blockIdx.z * KTOT;
        Bt += (size_t)blockIdx.z * KTOT;
        C  += (size_t)blockIdx.z * NG * DD;
    }

    const int w = tid >> 5, lane = tid & 31;
    const int wr = w >> 1, wc = w & 1;
    const int g = lane >> 2, cq = lane & 3;

    float acc[MT][NT][4];
    #pragma unroll
    for (int mt = 0; mt < MT; mt++)
        #pragma unroll
        for (int nt = 0; nt < NT; nt++)
            #pragma unroll
            for (int i = 0; i < 4; i++) acc[mt][nt][i] = 0.f;

    const int a_m = wr * WROWS + (lane & 7) + ((lane >> 3) & 1) * 8;
    const int a_kq = (lane >> 4) & 1;
    const int b_n = wc * (TN / 2) + (lane & 7) + ((lane >> 4) & 1) * 8;
    const int b_kq = (lane >> 3) & 1;

    load_tiles_h<TM, TN, KCH>(A, lda, Bt, ldb, row0, col0, 0, base, base + (uint32_t)TM * ROWB, tid);
    cp_commit();
    if (NC > 1) {
        load_tiles_h<TM, TN, KCH>(A, lda, Bt, ldb, row0, col0, KCH,
                                  base + STAGE, base + STAGE + (uint32_t)TM * ROWB, tid);
        cp_commit();
    }

    #pragma unroll
    for (int c = 0; c < NC; c++) {
        if (c + 1 < NC) cp_wait1(); else cp_wait0();
        __syncthreads();
        if (c + 2 < NC) {
            uint32_t a2 = base + (uint32_t)((c + 2) % 3) * STAGE;
            load_tiles_h<TM, TN, KCH>(A, lda, Bt, ldb, row0, col0, (c + 2) * KCH,
                                      a2, a2 + (uint32_t)TM * ROWB, tid);
            cp_commit();
        }
        uint32_t aS = base + (uint32_t)(c % 3) * STAGE, bS = aS + (uint32_t)TM * ROWB;
        #pragma unroll
        for (int kb = 0; kb < CH; kb += 2) {
            uint32_t af[MT][4];
            #pragma unroll
            for (int mt = 0; mt < MT; mt++) {
                int m = a_m + mt * 16;
                int kk = kb + a_kq;
                uint32_t sc = (uint32_t)(((kk ^ m) & 7) | (kk & ~7));
                uint32_t addr = aS + (uint32_t)m * ROWB + (sc << 4);
                LDSM4(af[mt][0], af[mt][1], af[mt][2], af[mt][3], addr);
            }
            uint32_t bf[NT][2];
            #pragma unroll
            for (int p = 0; p < NT / 2; p++) {
                int n = b_n + p * 16;
                int kk = kb + b_kq;
                uint32_t sc = (uint32_t)(((kk ^ n) & 7) | (kk & ~7));
                uint32_t addr = bS + (uint32_t)n * ROWB + (sc << 4);
                LDSM4(bf[2 * p][0], bf[2 * p][1], bf[2 * p + 1][0], bf[2 * p + 1][1], addr);
            }
            #pragma unroll
            for (int mt = 0; mt < MT; mt++)
                #pragma unroll
                for (int nt = 0; nt < NT; nt++)
                    mma16(acc[mt][nt], af[mt], bf[nt]);
        }
    }

    #pragma unroll
    for (int mt = 0; mt < MT; mt++) {
        #pragma unroll
        for (int nt = 0; nt < NT; nt++) {
            int cc = col0 + wc * (TN / 2) + nt * 8 + cq * 2;
            #pragma unroll
            for (int half = 0; half < 2; half++) {
                int r = row0 + wr * WROWS + mt * 16 + g + half * 8;
                float v0 = acc[mt][nt][half * 2];
                float v1 = acc[mt][nt][half * 2 + 1];
                if (MODE != 8) { v0 += bias[cc]; v1 += bias[cc + 1]; }
                if (MODE == 3) {
                    v0 += res[(size_t)r * ldc + cc];
                    v1 += res[(size_t)r * ldc + cc + 1];
                    float2 o; o.x = v0; o.y = v1;
                    *(float2*)(C + (size_t)r * ldc + cc) = o;
                } else if (MODE == 4) {
                    *(__half2*)(C16 + (size_t)r * ldc + cc) =
                        __floats2half2_rn(fmaxf(v0, 0.f), fmaxf(v1, 0.f));
                } else if (MODE == 6) {
                    *(__half2*)(C16 + (size_t)r * ldc + cc) = __floats2half2_rn(v0, v1);
                } else { // MODE 8: raw partial
                    float2 o; o.x = v0; o.y = v1;
                    *(float2*)(C + (size_t)r * ldc + cc) = o;
                }
            }
        }
    }
}

// ---------- launch ----------
static inline int smbh(int tm, int tn, int kch) { return 128 + 3 * (tm + tn) * kch * 2; }

extern "C" void kernel_launch(void* const* d_in, const int* in_sizes, int n_in,
                              void* d_out, int out_size)
{
    const float* x      = (const float*)d_in[0];
    const int*   sp     = (const int*)  d_in[1];
    const int*   deg    = (const int*)  d_in[3];
    const float* init_W = (const float*)d_in[4];
    const float* init_b = (const float*)d_in[5];
    const float* cent   = (const float*)d_in[6];
    const float* db     = (const float*)d_in[7];
    const float* vb     = (const float*)d_in[8];
    const float* Wq     = (const float*)d_in[9];
    const float* bq     = (const float*)d_in[10];
    const float* Wk     = (const float*)d_in[11];
    const float* bk     = (const float*)d_in[12];
    const float* Wv     = (const float*)d_in[13];
    const float* bv     = (const float*)d_in[14];
    const float* Wo     = (const float*)d_in[15];
    const float* bo     = (const float*)d_in[16];
    const float* W1     = (const float*)d_in[17];
    const float* b1     = (const float*)d_in[18];
    const float* W2     = (const float*)d_in[19];
    const float* b2     = (const float*)d_in[20];

    float *h, *bqkv, *part;
    __half *hn, *qkv, *attn, *ff, *WqkvT, *WoT, *W1T, *W2T;
    cudaGetSymbolAddress((void**)&h, g_h);
    cudaGetSymbolAddress((void**)&hn, g_hn);
    cudaGetSymbolAddress((void**)&qkv, g_qkv);
    cudaGetSymbolAddress((void**)&attn, g_attn);
    cudaGetSymbolAddress((void**)&ff, g_ff);
    cudaGetSymbolAddress((void**)&WqkvT, g_WqkvT);
    cudaGetSymbolAddress((void**)&bqkv, g_bqkv);
    cudaGetSymbolAddress((void**)&WoT, g_WoT);
    cudaGetSymbolAddress((void**)&W1T, g_W1T);
    cudaGetSymbolAddress((void**)&W2T, g_W2T);
    cudaGetSymbolAddress((void**)&part, g_part);

    cudaFuncSetAttribute((const void*)gemm_h<128, 128, 64, 512, 6>,   cudaFuncAttributeMaxDynamicSharedMemorySize, smbh(128, 128, 64));
    cudaFuncSetAttribute((const void*)gemm_h<128, 128, 64, 512, 4>,   cudaFuncAttributeMaxDynamicSharedMemorySize, smbh(128, 128, 64));
    cudaFuncSetAttribute((const void*)gemm_h<64, 64, 128, 512, 6>,    cudaFuncAttributeMaxDynamicSharedMemorySize, smbh(64, 64, 128));
    cudaFuncSetAttribute((const void*)gemm_h<64, 64, 128, 512, 4>,    cudaFuncAttributeMaxDynamicSharedMemorySize, smbh(64, 64, 128));
    cudaFuncSetAttribute((const void*)gemm_h<64, 64, 128, 512, 3>,    cudaFuncAttributeMaxDynamicSharedMemorySize, smbh(64, 64, 128));
    cudaFuncSetAttribute((const void*)gemm_h<64, 64, 128, 2048, 3>,   cudaFuncAttributeMaxDynamicSharedMemorySize, smbh(64, 64, 128));
    cudaFuncSetAttribute((const void*)gemm_h<64, 64, 128, 512, 8>,    cudaFuncAttributeMaxDynamicSharedMemorySize, smbh(64, 64, 128));

    // ---- packing + bias blocks ----
    fast_pack_qkvT<<<dim3(1, DD / 64, NL * 3 * NH), 256>>>(Wq, Wk, Wv, WqkvT);
    fast_transpose<<<dim3(DD / 64, DD / 64, NL), 256>>>(Wo, WoT, DD, DD);
    fast_transpose<<<dim3(FFD / 64, DD / 64, NL), 256>>>(W1, W1T, DD, FFD);
    fast_transpose<<<dim3(DD / 64, FFD / 64, NL), 256>>>(W2, W2T, FFD, DD);
    pack_bias<<<(NL * QKVW + 255) / 256, 256>>>(bq, bk, bv, bqkv);
    build_Bs<<<NG, 128>>>(sp, db, vb);

    init_h_kernel<<<(NN * DD) / 256, 256>>>(x, init_W, init_b, cent, deg);

    const float scale = 1.f / sqrtf((float)DKH);
    const size_t VOFF  = (size_t)N_ORIG * DD;
    const size_t VOFFQ = (size_t)N_ORIG * QKVW;

    for (int l = 0; l < NL; l++) {
        ln_kernel<<<NN / 8, 256>>>(h, hn);

        if (l < NL - 1) {
            gemm_h<128, 128, 64, 512, 6><<<dim3(QKVW / 128, NN / 128), 256, smbh(128, 128, 64)>>>(
                hn, DD, WqkvT + (size_t)l * QKVW * DD, DD, nullptr, qkv, QKVW,
                bqkv + (size_t)l * QKVW, nullptr);

            attn_fused<<<dim3(NG, NH), 128>>>(qkv, attn, scale, 0);

            gemm_h<64, 64, 128, 512, 3><<<dim3(DD / 64, NN / 64), 256, smbh(64, 64, 128)>>>(
                attn, DD, WoT + (size_t)l * DD * DD, DD, h, nullptr, DD,
                bo + (size_t)l * DD, h);

            ln_kernel<<<NN / 8, 256>>>(h, hn);

            gemm_h<128, 128, 64, 512, 4><<<dim3(FFD / 128, NN / 128), 256, smbh(128, 128, 64)>>>(
                hn, DD, W1T + (size_t)l * DD * FFD, DD, nullptr, ff, FFD,
                b1 + (size_t)l * FFD, nullptr);

            gemm_h<64, 64, 128, 2048, 3><<<dim3(DD / 64, NN / 64), 256, smbh(64, 64, 128)>>>(
                ff, FFD, W2T + (size_t)l * FFD * DD, FFD, h, nullptr, DD,
                b2 + (size_t)l * DD, h);
        } else {
            gemm_h<128, 128, 64, 512, 6><<<dim3((QKVW - DD) / 128, NN / 128), 256, smbh(128, 128, 64)>>>(
                hn, DD, WqkvT + (size_t)l * QKVW * DD + (size_t)DD * DD, DD,
                nullptr, qkv + DD, QKVW,
                bqkv + (size_t)l * QKVW + DD, nullptr);
            gemm_h<64, 64, 128, 512, 6><<<dim3(DD / 64, 1), 256, smbh(64, 64, 128)>>>(
                hn + VOFF, DD, WqkvT + (size_t)l * QKVW * DD, DD,
                nullptr, qkv + VOFFQ, QKVW,
                bqkv + (size_t)l * QKVW, nullptr);

            attn_fused<<<dim3(NG, NH), 128>>>(qkv, attn, scale, 1);

            gemm_h<64, 64, 128, 512, 3><<<dim3(DD / 64, 1), 256, smbh(64, 64, 128)>>>(
                attn + VOFF, DD, WoT + (size_t)l * DD * DD, DD, h + VOFF, nullptr, DD,
                bo + (size_t)l * DD, h + VOFF);

            ln_kernel<<<NG / 8, 256>>>(h + VOFF, hn + VOFF);

            gemm_h<64, 64, 128, 512, 4><<<dim3(FFD / 64, 1), 256, smbh(64, 64, 128)>>>(
                hn + VOFF, DD, W1T + (size_t)l * DD * FFD, DD, nullptr, ff, FFD,
                b1 + (size_t)l * FFD, nullptr);

            // final FFN2: split-K over 4 slices, then reduce into d_out
            gemm_h<64, 64, 128, 512, 8><<<dim3(DD / 64, 1, 4), 256, smbh(64, 64, 128)>>>(
                ff, FFD, W2T + (size_t)l * FFD * DD, FFD, part, nullptr, DD,
                nullptr, nullptr);
            reduce_out<<<(NG * DD) / 256, 256>>>(b2 + (size_t)l * DD, (float*)d_out);
        }
    }
}